// round 6
// baseline (speedup 1.0000x reference)
#include <cuda_runtime.h>
#include <cuda_fp16.h>
#include <cstdint>

#define NMAX 50000
#define EMAX 800000
#define H 64

// Scratch (static device arrays; no dynamic allocation allowed)
__device__ __half        g_h[NMAX * H];    // fp16 messages g = (X@W)*dinv_src
__device__ __half        g_a[NMAX * H];    // fp16 aggregated sums (layer boundary)
__device__ int           g_cnt[NMAX];      // incoming-edge count (excl self loop)
__device__ float         g_dinv[NMAX];
__device__ int           g_off[NMAX];      // CSR offsets
__device__ unsigned int  g_pack[EMAX];     // dst | (rank << 16)
__device__ int           g_csr[EMAX];      // CSR-sorted source ids per dst
__device__ float         g_colsum[H];
__device__ int           g_is64;

// decoupled-lookback scan state
__device__ int          g_ticket;
__device__ volatile int g_state[64];
__device__ volatile int g_aggval[64];
__device__ volatile int g_prefval[64];

// ---------------------------------------------------------------------------
__global__ void zero_kernel(const unsigned int* __restrict__ w, int N) {
    int i = blockIdx.x * blockDim.x + threadIdx.x;
    if (i < N) g_cnt[i] = 0;
    if (i < H) g_colsum[i] = 0.f;
    if (i < 64) ((int*)g_state)[i] = 0;
    if (i == 0) g_ticket = 0;
    if (blockIdx.x == 0 && threadIdx.x < 32) {
        unsigned int v = w[2 * threadIdx.x + 1] | w[2 * (threadIdx.x + 32) + 1];
        int all0 = __all_sync(0xffffffffu, v == 0u);
        if (threadIdx.x == 0) g_is64 = all0;
    }
}

// Histogram + pack(dst, rank). 4 edges/thread for atomic MLP.
__global__ void hist_kernel(const int* __restrict__ ei, int E) {
    int base = (blockIdx.x * blockDim.x + threadIdx.x) * 4;
    bool is64 = g_is64;
    if (base + 3 < E) {
        int d0 = is64 ? ei[2 * E + 2 * (base + 0)] : ei[E + base + 0];
        int d1 = is64 ? ei[2 * E + 2 * (base + 1)] : ei[E + base + 1];
        int d2 = is64 ? ei[2 * E + 2 * (base + 2)] : ei[E + base + 2];
        int d3 = is64 ? ei[2 * E + 2 * (base + 3)] : ei[E + base + 3];
        unsigned int r0 = atomicAdd(&g_cnt[d0], 1);
        unsigned int r1 = atomicAdd(&g_cnt[d1], 1);
        unsigned int r2 = atomicAdd(&g_cnt[d2], 1);
        unsigned int r3 = atomicAdd(&g_cnt[d3], 1);
        g_pack[base + 0] = (unsigned int)d0 | (r0 << 16);
        g_pack[base + 1] = (unsigned int)d1 | (r1 << 16);
        g_pack[base + 2] = (unsigned int)d2 | (r2 << 16);
        g_pack[base + 3] = (unsigned int)d3 | (r3 << 16);
    } else {
        for (int j = 0; j < 4; j++) {
            int e = base + j;
            if (e < E) {
                int d = is64 ? ei[2 * E + 2 * e] : ei[E + e];
                unsigned int r = atomicAdd(&g_cnt[d], 1);
                g_pack[e] = (unsigned int)d | (r << 16);
            }
        }
    }
}

// ---------------------------------------------------------------------------
// Single-kernel exclusive scan (decoupled lookback, ticket-ordered).
// ---------------------------------------------------------------------------
__global__ void scan_kernel(int N) {
    __shared__ int s_bid;
    __shared__ int s_warp[8];
    __shared__ int s_exc;
    int t = threadIdx.x;
    if (t == 0) s_bid = atomicAdd(&g_ticket, 1);
    __syncthreads();
    int bid = s_bid;

    int base = bid * 1024 + t * 4;
    int v[4], tsum = 0;
#pragma unroll
    for (int j = 0; j < 4; j++) {
        int idx = base + j;
        v[j] = (idx < N) ? g_cnt[idx] : 0;
        tsum += v[j];
    }
    int lane = t & 31, w = t >> 5;
    int x = tsum;
#pragma unroll
    for (int o = 1; o < 32; o <<= 1) {
        int y = __shfl_up_sync(0xffffffffu, x, o);
        if (lane >= o) x += y;
    }
    if (lane == 31) s_warp[w] = x;
    __syncthreads();

    if (t == 0) {
        int total = 0;
#pragma unroll
        for (int i = 0; i < 8; i++) { int tmp = s_warp[i]; s_warp[i] = total; total += tmp; }
        int exc = 0;
        if (bid == 0) {
            g_prefval[0] = total;
            __threadfence();
            g_state[0] = 2;
        } else {
            g_aggval[bid] = total;
            __threadfence();
            g_state[bid] = 1;
            int i = bid - 1;
            while (true) {
                int st;
                while ((st = g_state[i]) == 0) { }
                if (st == 2) { exc += g_prefval[i]; break; }
                exc += g_aggval[i];
                i--;
            }
            g_prefval[bid] = exc + total;
            __threadfence();
            g_state[bid] = 2;
        }
        s_exc = exc;
    }
    __syncthreads();

    int run = x - tsum + s_warp[w] + s_exc;
#pragma unroll
    for (int j = 0; j < 4; j++) {
        int idx = base + j;
        if (idx < N) {
            g_off[idx]  = run;
            g_dinv[idx] = rsqrtf((float)(v[j] + 1));   // +1 self loop
            run += v[j];
        }
    }
}

// Atomic-free CSR fill: pos = off[dst] + rank, from packed word + src column.
__global__ void fill_kernel(const int* __restrict__ ei, int E) {
    int base = (blockIdx.x * blockDim.x + threadIdx.x) * 4;
    bool is64 = g_is64;
#pragma unroll
    for (int j = 0; j < 4; j++) {
        int e = base + j;
        if (e < E) {
            int s = is64 ? ei[2 * e] : ei[e];
            unsigned int p = g_pack[e];
            int d = (int)(p & 0xffffu);
            int r = (int)(p >> 16);
            g_csr[g_off[d] + r] = s;
        }
    }
}

// ---------------------------------------------------------------------------
// Gather helpers: 4 threads/node, each owns 16 features (2x16B fp16 chunks).
// Edge loop unrolled x4 => 8 independent LDG.128 in flight per thread.
// ---------------------------------------------------------------------------
__device__ __forceinline__ void acc16(float* a, uint4 r0, uint4 r1) {
    const unsigned int rr[8] = {r0.x, r0.y, r0.z, r0.w, r1.x, r1.y, r1.z, r1.w};
#pragma unroll
    for (int q = 0; q < 8; q++) {
        __half2 h = *reinterpret_cast<const __half2*>(&rr[q]);
        float2 f = __half22float2(h);
        a[2 * q]     += f.x;
        a[2 * q + 1] += f.y;
    }
}

__device__ __forceinline__ void gather_node(float* a, int gn, int lane) {
    const uint4* gh = (const uint4*)g_h;   // 8 uint4 per node row
#pragma unroll
    for (int j = 0; j < 16; j++) a[j] = 0.f;
    {   // self message
        uint4 r0 = __ldg(gh + (size_t)gn * 8 + lane * 2);
        uint4 r1 = __ldg(gh + (size_t)gn * 8 + lane * 2 + 1);
        acc16(a, r0, r1);
    }
    int e = g_off[gn];
    int end = e + g_cnt[gn];
    for (; e + 4 <= end; e += 4) {
        int s0 = __ldg(&g_csr[e]);
        int s1 = __ldg(&g_csr[e + 1]);
        int s2 = __ldg(&g_csr[e + 2]);
        int s3 = __ldg(&g_csr[e + 3]);
        uint4 a0 = __ldg(gh + (size_t)s0 * 8 + lane * 2);
        uint4 a1 = __ldg(gh + (size_t)s0 * 8 + lane * 2 + 1);
        uint4 b0 = __ldg(gh + (size_t)s1 * 8 + lane * 2);
        uint4 b1 = __ldg(gh + (size_t)s1 * 8 + lane * 2 + 1);
        uint4 c0 = __ldg(gh + (size_t)s2 * 8 + lane * 2);
        uint4 c1 = __ldg(gh + (size_t)s2 * 8 + lane * 2 + 1);
        uint4 d0 = __ldg(gh + (size_t)s3 * 8 + lane * 2);
        uint4 d1 = __ldg(gh + (size_t)s3 * 8 + lane * 2 + 1);
        acc16(a, a0, a1);
        acc16(a, b0, b1);
        acc16(a, c0, c1);
        acc16(a, d0, d1);
    }
    for (; e < end; e++) {
        int s = __ldg(&g_csr[e]);
        uint4 r0 = __ldg(gh + (size_t)s * 8 + lane * 2);
        uint4 r1 = __ldg(gh + (size_t)s * 8 + lane * 2 + 1);
        acc16(a, r0, r1);
    }
}

// Separate aggregate kernel: imbalance hidden by warp oversubscription.
// Writes raw fp16 sums to g_a (epilogue applied by the next GEMM's loader).
__global__ __launch_bounds__(256) void agg_kernel(int N) {
    int idx = blockIdx.x * blockDim.x + threadIdx.x;
    int node = idx >> 2, lane = idx & 3;
    if (node >= N) return;
    float a[16];
    gather_node(a, node, lane);
    unsigned int wbuf[8];
#pragma unroll
    for (int q = 0; q < 8; q++) {
        __half2 h = __floats2half2_rn(a[2 * q], a[2 * q + 1]);
        wbuf[q] = *reinterpret_cast<unsigned int*>(&h);
    }
    uint4* dst = (uint4*)(g_a + (size_t)node * H + lane * 16);
    dst[0] = make_uint4(wbuf[0], wbuf[1], wbuf[2], wbuf[3]);
    dst[1] = make_uint4(wbuf[4], wbuf[5], wbuf[6], wbuf[7]);
}

// Final aggregate fused with mean pooling column sums (no g_a write).
__global__ __launch_bounds__(256) void aggfinal_kernel(int N) {
    __shared__ float s_col[H];
    if (threadIdx.x < H) s_col[threadIdx.x] = 0.f;
    __syncthreads();

    int idx = blockIdx.x * blockDim.x + threadIdx.x;
    int node = idx >> 2, lane = idx & 3;
    if (node < N) {
        float a[16];
        gather_node(a, node, lane);
        float di = g_dinv[node];
#pragma unroll
        for (int j = 0; j < 16; j++)
            atomicAdd(&s_col[lane * 16 + j], a[j] * di);
    }
    __syncthreads();
    if (threadIdx.x < H) atomicAdd(&g_colsum[threadIdx.x], s_col[threadIdx.x]);
}

// ---------------------------------------------------------------------------
// Layer 1 GEMM: x[N,10] @ W1[10,64], scale by dinv, write fp16 messages.
// ---------------------------------------------------------------------------
__global__ __launch_bounds__(256) void gemm1_kernel(const float* __restrict__ X,
                                                    const float* __restrict__ W,
                                                    int N) {
    __shared__ float xs[64][12];
    __shared__ float ws[10][64];
    int node0 = blockIdx.x * 64;
    int t = threadIdx.x;

    for (int i = t; i < 640; i += 256) ws[i >> 6][i & 63] = W[i];
    for (int i = t; i < 640; i += 256) {
        int n = i / 10, k = i - n * 10;
        int gn = node0 + n;
        xs[n][k] = (gn < N) ? X[gn * 10 + k] : 0.f;
    }
    __syncthreads();

    int tx = t & 15, ty = t >> 4;
    float acc[4][4];
#pragma unroll
    for (int i = 0; i < 4; i++)
#pragma unroll
        for (int j = 0; j < 4; j++) acc[i][j] = 0.f;

#pragma unroll
    for (int k = 0; k < 10; k++) {
        float4 wv = *(const float4*)&ws[k][tx * 4];
#pragma unroll
        for (int i = 0; i < 4; i++) {
            float xa = xs[ty * 4 + i][k];
            acc[i][0] = fmaf(xa, wv.x, acc[i][0]);
            acc[i][1] = fmaf(xa, wv.y, acc[i][1]);
            acc[i][2] = fmaf(xa, wv.z, acc[i][2]);
            acc[i][3] = fmaf(xa, wv.w, acc[i][3]);
        }
    }

#pragma unroll
    for (int i = 0; i < 4; i++) {
        int gn = node0 + ty * 4 + i;
        if (gn < N) {
            float di = g_dinv[gn];
            __half2* hp = (__half2*)(g_h + (size_t)gn * H + tx * 4);
            hp[0] = __floats2half2_rn(acc[i][0] * di, acc[i][1] * di);
            hp[1] = __floats2half2_rn(acc[i][2] * di, acc[i][3] * di);
        }
    }
}

// ---------------------------------------------------------------------------
// Layers 2/3 GEMM: input = relu(g_a * dinv + bias_prev)  (fp16 g_a load),
// 64x64x64 per block, scale output by dinv, write fp16 messages to g_h.
// ---------------------------------------------------------------------------
__global__ __launch_bounds__(256) void gemm2_kernel(const float* __restrict__ W,
                                                    const float* __restrict__ bias_prev,
                                                    int N) {
    __shared__ float xs[64][68];
    __shared__ float ws[64][64];
    __shared__ float bsh[64];

    int node0 = blockIdx.x * 64;
    int t = threadIdx.x;

    for (int i = t; i < 4096; i += 256) ws[i >> 6][i & 63] = W[i];
    if (t < 64) bsh[t] = bias_prev[t];
    __syncthreads();

    // Load + epilogue: 512 chunks of 8 fp16 (2 per thread)
    for (int i = t; i < 512; i += 256) {
        int n = i >> 3, c = i & 7;
        int gn = node0 + n;
        if (gn < N) {
            uint4 r = __ldg((const uint4*)(g_a + (size_t)gn * H + c * 8));
            float di = g_dinv[gn];
            const unsigned int rr[4] = {r.x, r.y, r.z, r.w};
#pragma unroll
            for (int q = 0; q < 4; q++) {
                float2 f = __half22float2(*reinterpret_cast<const __half2*>(&rr[q]));
                xs[n][c * 8 + 2 * q]     = fmaxf(fmaf(f.x, di, bsh[c * 8 + 2 * q]), 0.f);
                xs[n][c * 8 + 2 * q + 1] = fmaxf(fmaf(f.y, di, bsh[c * 8 + 2 * q + 1]), 0.f);
            }
        } else {
#pragma unroll
            for (int q = 0; q < 8; q++) xs[n][c * 8 + q] = 0.f;
        }
    }
    __syncthreads();

    int tx = t & 15, ty = t >> 4;
    float acc[4][4];
#pragma unroll
    for (int i = 0; i < 4; i++)
#pragma unroll
        for (int j = 0; j < 4; j++) acc[i][j] = 0.f;

#pragma unroll
    for (int k = 0; k < 64; k++) {
        float4 wv = *(const float4*)&ws[k][tx * 4];
#pragma unroll
        for (int i = 0; i < 4; i++) {
            float xa = xs[ty * 4 + i][k];
            acc[i][0] = fmaf(xa, wv.x, acc[i][0]);
            acc[i][1] = fmaf(xa, wv.y, acc[i][1]);
            acc[i][2] = fmaf(xa, wv.z, acc[i][2]);
            acc[i][3] = fmaf(xa, wv.w, acc[i][3]);
        }
    }

#pragma unroll
    for (int i = 0; i < 4; i++) {
        int gn = node0 + ty * 4 + i;
        if (gn < N) {
            float di = g_dinv[gn];
            __half2* hp = (__half2*)(g_h + (size_t)gn * H + tx * 4);
            hp[0] = __floats2half2_rn(acc[i][0] * di, acc[i][1] * di);
            hp[1] = __floats2half2_rn(acc[i][2] * di, acc[i][3] * di);
        }
    }
}

// out = (colsum/N + b3) . fcW + fcb
__global__ void final_kernel(const float* __restrict__ b3,
                             const float* __restrict__ fcW,
                             const float* __restrict__ fcb,
                             float* __restrict__ out, int N) {
    int f = threadIdx.x;  // 64 threads
    float v = (g_colsum[f] / (float)N + b3[f]) * fcW[f];
#pragma unroll
    for (int o = 16; o > 0; o >>= 1) v += __shfl_down_sync(0xffffffffu, v, o);
    __shared__ float p[2];
    if ((f & 31) == 0) p[f >> 5] = v;
    __syncthreads();
    if (f == 0) out[0] = p[0] + p[1] + fcb[0];
}

extern "C" void kernel_launch(void* const* d_in, const int* in_sizes, int n_in,
                              void* d_out, int out_size) {
    const float* x   = (const float*)d_in[0];
    const void*  ei  = d_in[1];
    const float* W1  = (const float*)d_in[2];
    const float* b1  = (const float*)d_in[3];
    const float* W2  = (const float*)d_in[4];
    const float* b2  = (const float*)d_in[5];
    const float* W3  = (const float*)d_in[6];
    const float* b3  = (const float*)d_in[7];
    const float* fcW = (const float*)d_in[8];
    const float* fcb = (const float*)d_in[9];
    float* out = (float*)d_out;

    int FIN1 = in_sizes[2] / H;      // 10
    int N = in_sizes[0] / FIN1;      // 50000
    int E = in_sizes[1] / 2;         // 800000

    int SB = (N + 1023) / 1024;              // scan blocks (<=64)
    int eblocks = (E + 1023) / 1024;         // 4 edges/thread
    int gblocks = (N + 63) / 64;
    int fblocks = (N * 4 + 255) / 256;

    zero_kernel<<<(N + 255) / 256, 256>>>((const unsigned int*)ei, N);
    hist_kernel<<<eblocks, 256>>>((const int*)ei, E);
    scan_kernel<<<SB, 256>>>(N);
    fill_kernel<<<eblocks, 256>>>((const int*)ei, E);

    gemm1_kernel<<<gblocks, 256>>>(x, W1, N);    // -> g_h
    agg_kernel<<<fblocks, 256>>>(N);             // g_h -> g_a
    gemm2_kernel<<<gblocks, 256>>>(W2, b1, N);   // g_a -> g_h
    agg_kernel<<<fblocks, 256>>>(N);             // g_h -> g_a
    gemm2_kernel<<<gblocks, 256>>>(W3, b2, N);   // g_a -> g_h
    aggfinal_kernel<<<fblocks, 256>>>(N);        // g_h -> colsum
    final_kernel<<<1, 64>>>(b3, fcW, fcb, out, N);
}

// round 7
// speedup vs baseline: 1.2027x; 1.2027x over previous
#include <cuda_runtime.h>
#include <cuda_fp16.h>
#include <cstdint>

#define NMAX 50000
#define EMAX 800000
#define H 64

// Scratch (static device arrays; no dynamic allocation allowed)
__device__ __half        g_h[NMAX * H];    // fp16 messages g = (X@W)*dinv_src
__device__ __half        g_a[NMAX * H];    // fp16 aggregated sums (layer boundary)
__device__ int           g_cnt[NMAX];      // incoming-edge count (excl self loop)
__device__ float         g_dinv[NMAX];
__device__ int           g_off[NMAX];      // CSR offsets
__device__ unsigned int  g_pack[EMAX];     // dst | (rank << 16)
__device__ int           g_csr[EMAX];      // CSR-sorted source ids per dst
__device__ float         g_colsum[H];
__device__ int           g_is64;

// decoupled-lookback scan state
__device__ int          g_ticket;
__device__ volatile int g_state[64];
__device__ volatile int g_aggval[64];
__device__ volatile int g_prefval[64];

// ---------------------------------------------------------------------------
// 1-warp kernel: detect int64 vs int32 edge_index + zero small state.
// ---------------------------------------------------------------------------
__global__ void detect_kernel(const unsigned int* __restrict__ w) {
    int t = threadIdx.x;
    unsigned int v = w[2 * t + 1] | w[2 * (t + 32) + 1];
    int all0 = __all_sync(0xffffffffu, v == 0u);
    if (t == 0) { g_is64 = all0; g_ticket = 0; }
    ((int*)g_state)[t] = 0;
    ((int*)g_state)[t + 32] = 0;
    g_colsum[t] = 0.f;
    g_colsum[t + 32] = 0.f;
}

// Histogram + pack(dst, rank). 4 edges/thread for atomic MLP.
__global__ void hist_kernel(const int* __restrict__ ei, int E) {
    int base = (blockIdx.x * blockDim.x + threadIdx.x) * 4;
    bool is64 = g_is64;
    if (base + 3 < E) {
        int d0 = is64 ? ei[2 * E + 2 * (base + 0)] : ei[E + base + 0];
        int d1 = is64 ? ei[2 * E + 2 * (base + 1)] : ei[E + base + 1];
        int d2 = is64 ? ei[2 * E + 2 * (base + 2)] : ei[E + base + 2];
        int d3 = is64 ? ei[2 * E + 2 * (base + 3)] : ei[E + base + 3];
        unsigned int r0 = atomicAdd(&g_cnt[d0], 1);
        unsigned int r1 = atomicAdd(&g_cnt[d1], 1);
        unsigned int r2 = atomicAdd(&g_cnt[d2], 1);
        unsigned int r3 = atomicAdd(&g_cnt[d3], 1);
        g_pack[base + 0] = (unsigned int)d0 | (r0 << 16);
        g_pack[base + 1] = (unsigned int)d1 | (r1 << 16);
        g_pack[base + 2] = (unsigned int)d2 | (r2 << 16);
        g_pack[base + 3] = (unsigned int)d3 | (r3 << 16);
    } else {
        for (int j = 0; j < 4; j++) {
            int e = base + j;
            if (e < E) {
                int d = is64 ? ei[2 * E + 2 * e] : ei[E + e];
                unsigned int r = atomicAdd(&g_cnt[d], 1);
                g_pack[e] = (unsigned int)d | (r << 16);
            }
        }
    }
}

// ---------------------------------------------------------------------------
// Single-kernel exclusive scan (decoupled lookback, ticket-ordered).
// ---------------------------------------------------------------------------
__global__ void scan_kernel(int N) {
    __shared__ int s_bid;
    __shared__ int s_warp[8];
    __shared__ int s_exc;
    int t = threadIdx.x;
    if (t == 0) s_bid = atomicAdd(&g_ticket, 1);
    __syncthreads();
    int bid = s_bid;

    int base = bid * 1024 + t * 4;
    int v[4], tsum = 0;
#pragma unroll
    for (int j = 0; j < 4; j++) {
        int idx = base + j;
        v[j] = (idx < N) ? g_cnt[idx] : 0;
        tsum += v[j];
    }
    int lane = t & 31, w = t >> 5;
    int x = tsum;
#pragma unroll
    for (int o = 1; o < 32; o <<= 1) {
        int y = __shfl_up_sync(0xffffffffu, x, o);
        if (lane >= o) x += y;
    }
    if (lane == 31) s_warp[w] = x;
    __syncthreads();

    if (t == 0) {
        int total = 0;
#pragma unroll
        for (int i = 0; i < 8; i++) { int tmp = s_warp[i]; s_warp[i] = total; total += tmp; }
        int exc = 0;
        if (bid == 0) {
            g_prefval[0] = total;
            __threadfence();
            g_state[0] = 2;
        } else {
            g_aggval[bid] = total;
            __threadfence();
            g_state[bid] = 1;
            int i = bid - 1;
            while (true) {
                int st;
                while ((st = g_state[i]) == 0) { }
                if (st == 2) { exc += g_prefval[i]; break; }
                exc += g_aggval[i];
                i--;
            }
            g_prefval[bid] = exc + total;
            __threadfence();
            g_state[bid] = 2;
        }
        s_exc = exc;
    }
    __syncthreads();

    int run = x - tsum + s_warp[w] + s_exc;
#pragma unroll
    for (int j = 0; j < 4; j++) {
        int idx = base + j;
        if (idx < N) {
            g_off[idx]  = run;
            g_dinv[idx] = rsqrtf((float)(v[j] + 1));   // +1 self loop
            run += v[j];
        }
    }
}

// Atomic-free CSR fill: pos = off[dst] + rank, from packed word + src column.
__global__ void fill_kernel(const int* __restrict__ ei, int E) {
    int base = (blockIdx.x * blockDim.x + threadIdx.x) * 4;
    bool is64 = g_is64;
#pragma unroll
    for (int j = 0; j < 4; j++) {
        int e = base + j;
        if (e < E) {
            int s = is64 ? ei[2 * e] : ei[e];
            unsigned int p = g_pack[e];
            int d = (int)(p & 0xffffu);
            int r = (int)(p >> 16);
            g_csr[g_off[d] + r] = s;
        }
    }
}

// ---------------------------------------------------------------------------
// Gather: 8 threads/node, each owns 8 features = one uint4 of fp16 per edge.
// Edge loop unrolled x4 => 4 independent LDG.128 in flight per thread, and
// 2x the warps of a 4-thread/node split to hide L2 latency + degree tails.
// ---------------------------------------------------------------------------
__device__ __forceinline__ void acc8(float* a, uint4 r) {
    const unsigned int rr[4] = {r.x, r.y, r.z, r.w};
#pragma unroll
    for (int q = 0; q < 4; q++) {
        float2 f = __half22float2(*reinterpret_cast<const __half2*>(&rr[q]));
        a[2 * q]     += f.x;
        a[2 * q + 1] += f.y;
    }
}

__device__ __forceinline__ void gather_node(float* a, int gn, int lane) {
    const uint4* gh = (const uint4*)g_h;   // 8 uint4 per node row
#pragma unroll
    for (int j = 0; j < 8; j++) a[j] = 0.f;
    acc8(a, __ldg(gh + (size_t)gn * 8 + lane));   // self message
    int e = g_off[gn];
    int end = e + g_cnt[gn];
    for (; e + 4 <= end; e += 4) {
        int s0 = __ldg(&g_csr[e]);
        int s1 = __ldg(&g_csr[e + 1]);
        int s2 = __ldg(&g_csr[e + 2]);
        int s3 = __ldg(&g_csr[e + 3]);
        uint4 r0 = __ldg(gh + (size_t)s0 * 8 + lane);
        uint4 r1 = __ldg(gh + (size_t)s1 * 8 + lane);
        uint4 r2 = __ldg(gh + (size_t)s2 * 8 + lane);
        uint4 r3 = __ldg(gh + (size_t)s3 * 8 + lane);
        acc8(a, r0);
        acc8(a, r1);
        acc8(a, r2);
        acc8(a, r3);
    }
    for (; e < end; e++) {
        int s = __ldg(&g_csr[e]);
        acc8(a, __ldg(gh + (size_t)s * 8 + lane));
    }
}

// Aggregate: raw fp16 sums to g_a (epilogue applied by the next GEMM loader).
__global__ __launch_bounds__(256) void agg_kernel(int N) {
    int idx = blockIdx.x * blockDim.x + threadIdx.x;
    int node = idx >> 3, lane = idx & 7;
    if (node >= N) return;
    float a[8];
    gather_node(a, node, lane);
    unsigned int wbuf[4];
#pragma unroll
    for (int q = 0; q < 4; q++) {
        __half2 h = __floats2half2_rn(a[2 * q], a[2 * q + 1]);
        wbuf[q] = *reinterpret_cast<unsigned int*>(&h);
    }
    *(uint4*)(g_a + (size_t)node * H + lane * 8) =
        make_uint4(wbuf[0], wbuf[1], wbuf[2], wbuf[3]);
}

// Final aggregate fused with mean pooling column sums (no g_a write).
__global__ __launch_bounds__(256) void aggfinal_kernel(int N) {
    __shared__ float s_col[H];
    if (threadIdx.x < H) s_col[threadIdx.x] = 0.f;
    __syncthreads();

    int idx = blockIdx.x * blockDim.x + threadIdx.x;
    int node = idx >> 3, lane = idx & 7;
    if (node < N) {
        float a[8];
        gather_node(a, node, lane);
        float di = g_dinv[node];
#pragma unroll
        for (int j = 0; j < 8; j++)
            atomicAdd(&s_col[lane * 8 + j], a[j] * di);
    }
    __syncthreads();
    if (threadIdx.x < H) atomicAdd(&g_colsum[threadIdx.x], s_col[threadIdx.x]);
}

// ---------------------------------------------------------------------------
// Layer 1 GEMM: x[N,10] @ W1[10,64], scale by dinv, write fp16 messages.
// ---------------------------------------------------------------------------
__global__ __launch_bounds__(256) void gemm1_kernel(const float* __restrict__ X,
                                                    const float* __restrict__ W,
                                                    int N) {
    __shared__ float xs[64][12];
    __shared__ float ws[10][64];
    int node0 = blockIdx.x * 64;
    int t = threadIdx.x;

    for (int i = t; i < 640; i += 256) ws[i >> 6][i & 63] = W[i];
    for (int i = t; i < 640; i += 256) {
        int n = i / 10, k = i - n * 10;
        int gn = node0 + n;
        xs[n][k] = (gn < N) ? X[gn * 10 + k] : 0.f;
    }
    __syncthreads();

    int tx = t & 15, ty = t >> 4;
    float acc[4][4];
#pragma unroll
    for (int i = 0; i < 4; i++)
#pragma unroll
        for (int j = 0; j < 4; j++) acc[i][j] = 0.f;

#pragma unroll
    for (int k = 0; k < 10; k++) {
        float4 wv = *(const float4*)&ws[k][tx * 4];
#pragma unroll
        for (int i = 0; i < 4; i++) {
            float xa = xs[ty * 4 + i][k];
            acc[i][0] = fmaf(xa, wv.x, acc[i][0]);
            acc[i][1] = fmaf(xa, wv.y, acc[i][1]);
            acc[i][2] = fmaf(xa, wv.z, acc[i][2]);
            acc[i][3] = fmaf(xa, wv.w, acc[i][3]);
        }
    }

#pragma unroll
    for (int i = 0; i < 4; i++) {
        int gn = node0 + ty * 4 + i;
        if (gn < N) {
            float di = g_dinv[gn];
            __half2* hp = (__half2*)(g_h + (size_t)gn * H + tx * 4);
            hp[0] = __floats2half2_rn(acc[i][0] * di, acc[i][1] * di);
            hp[1] = __floats2half2_rn(acc[i][2] * di, acc[i][3] * di);
        }
    }
}

// ---------------------------------------------------------------------------
// Layers 2/3 GEMM: input = relu(g_a * dinv + bias_prev)  (fp16 g_a load),
// 64x64x64 per block, scale output by dinv, write fp16 messages to g_h.
// ---------------------------------------------------------------------------
__global__ __launch_bounds__(256) void gemm2_kernel(const float* __restrict__ W,
                                                    const float* __restrict__ bias_prev,
                                                    int N) {
    __shared__ float xs[64][68];
    __shared__ float ws[64][64];
    __shared__ float bsh[64];

    int node0 = blockIdx.x * 64;
    int t = threadIdx.x;

    for (int i = t; i < 4096; i += 256) ws[i >> 6][i & 63] = W[i];
    if (t < 64) bsh[t] = bias_prev[t];
    __syncthreads();

    // Load + epilogue: 512 chunks of 8 fp16 (2 per thread)
    for (int i = t; i < 512; i += 256) {
        int n = i >> 3, c = i & 7;
        int gn = node0 + n;
        if (gn < N) {
            uint4 r = __ldg((const uint4*)(g_a + (size_t)gn * H + c * 8));
            float di = g_dinv[gn];
            const unsigned int rr[4] = {r.x, r.y, r.z, r.w};
#pragma unroll
            for (int q = 0; q < 4; q++) {
                float2 f = __half22float2(*reinterpret_cast<const __half2*>(&rr[q]));
                xs[n][c * 8 + 2 * q]     = fmaxf(fmaf(f.x, di, bsh[c * 8 + 2 * q]), 0.f);
                xs[n][c * 8 + 2 * q + 1] = fmaxf(fmaf(f.y, di, bsh[c * 8 + 2 * q + 1]), 0.f);
            }
        } else {
#pragma unroll
            for (int q = 0; q < 8; q++) xs[n][c * 8 + q] = 0.f;
        }
    }
    __syncthreads();

    int tx = t & 15, ty = t >> 4;
    float acc[4][4];
#pragma unroll
    for (int i = 0; i < 4; i++)
#pragma unroll
        for (int j = 0; j < 4; j++) acc[i][j] = 0.f;

#pragma unroll
    for (int k = 0; k < 64; k++) {
        float4 wv = *(const float4*)&ws[k][tx * 4];
#pragma unroll
        for (int i = 0; i < 4; i++) {
            float xa = xs[ty * 4 + i][k];
            acc[i][0] = fmaf(xa, wv.x, acc[i][0]);
            acc[i][1] = fmaf(xa, wv.y, acc[i][1]);
            acc[i][2] = fmaf(xa, wv.z, acc[i][2]);
            acc[i][3] = fmaf(xa, wv.w, acc[i][3]);
        }
    }

#pragma unroll
    for (int i = 0; i < 4; i++) {
        int gn = node0 + ty * 4 + i;
        if (gn < N) {
            float di = g_dinv[gn];
            __half2* hp = (__half2*)(g_h + (size_t)gn * H + tx * 4);
            hp[0] = __floats2half2_rn(acc[i][0] * di, acc[i][1] * di);
            hp[1] = __floats2half2_rn(acc[i][2] * di, acc[i][3] * di);
        }
    }
}

// out = (colsum/N + b3) . fcW + fcb
__global__ void final_kernel(const float* __restrict__ b3,
                             const float* __restrict__ fcW,
                             const float* __restrict__ fcb,
                             float* __restrict__ out, int N) {
    int f = threadIdx.x;  // 64 threads
    float v = (g_colsum[f] / (float)N + b3[f]) * fcW[f];
#pragma unroll
    for (int o = 16; o > 0; o >>= 1) v += __shfl_down_sync(0xffffffffu, v, o);
    __shared__ float p[2];
    if ((f & 31) == 0) p[f >> 5] = v;
    __syncthreads();
    if (f == 0) out[0] = p[0] + p[1] + fcb[0];
}

extern "C" void kernel_launch(void* const* d_in, const int* in_sizes, int n_in,
                              void* d_out, int out_size) {
    const float* x   = (const float*)d_in[0];
    const void*  ei  = d_in[1];
    const float* W1  = (const float*)d_in[2];
    const float* b1  = (const float*)d_in[3];
    const float* W2  = (const float*)d_in[4];
    const float* b2  = (const float*)d_in[5];
    const float* W3  = (const float*)d_in[6];
    const float* b3  = (const float*)d_in[7];
    const float* fcW = (const float*)d_in[8];
    const float* fcb = (const float*)d_in[9];
    float* out = (float*)d_out;

    int FIN1 = in_sizes[2] / H;      // 10
    int N = in_sizes[0] / FIN1;      // 50000
    int E = in_sizes[1] / 2;         // 800000

    int SB = (N + 1023) / 1024;              // scan blocks (<=64)
    int eblocks = (E + 1023) / 1024;         // 4 edges/thread
    int gblocks = (N + 63) / 64;
    int ablocks = (N * 8 + 255) / 256;

    // Zero g_cnt via memset node (graph-capturable, no allocation).
    void* cnt_ptr = nullptr;
    cudaGetSymbolAddress(&cnt_ptr, g_cnt);
    cudaMemsetAsync(cnt_ptr, 0, (size_t)N * sizeof(int));

    detect_kernel<<<1, 32>>>((const unsigned int*)ei);
    hist_kernel<<<eblocks, 256>>>((const int*)ei, E);
    scan_kernel<<<SB, 256>>>(N);
    fill_kernel<<<eblocks, 256>>>((const int*)ei, E);

    gemm1_kernel<<<gblocks, 256>>>(x, W1, N);    // -> g_h
    agg_kernel<<<ablocks, 256>>>(N);             // g_h -> g_a
    gemm2_kernel<<<gblocks, 256>>>(W2, b1, N);   // g_a -> g_h
    agg_kernel<<<ablocks, 256>>>(N);             // g_h -> g_a
    gemm2_kernel<<<gblocks, 256>>>(W3, b2, N);   // g_a -> g_h
    aggfinal_kernel<<<ablocks, 256>>>(N);        // g_h -> colsum
    final_kernel<<<1, 64>>>(b3, fcW, fcb, out, N);
}

// round 9
// speedup vs baseline: 1.2827x; 1.0665x over previous
#include <cuda_runtime.h>
#include <cuda_fp16.h>
#include <mma.h>
#include <cstdint>

using namespace nvcuda;

#define NMAX 50000
#define EMAX 800000
#define H 64

// Scratch (static device arrays; no dynamic allocation allowed)
__device__ __half        g_h[NMAX * H];    // fp16 messages g = (X@W)*dinv_src
__device__ __half        g_a[NMAX * H];    // fp16 aggregated sums (layer boundary)
__device__ int           g_cnt[NMAX];      // incoming-edge count (excl self loop)
__device__ float         g_dinv[NMAX];
__device__ int           g_off[NMAX];      // CSR offsets
__device__ unsigned int  g_pack[EMAX];     // dst | (rank << 16)
__device__ int           g_csr[EMAX];      // CSR-sorted source ids per dst

// Control block zeroed by one memset
struct Ctl {
    int   ticket;
    int   state[64];     // 0=invalid 1=aggregate 2=prefix
    float colsum[H];
};
__device__ Ctl g_ctl;
__device__ int g_aggval[64];    // guarded by state; no zeroing needed
__device__ int g_prefval[64];

// ---------------------------------------------------------------------------
// Per-block int64/int32 detection (values < 50000 => odd 32-bit words all 0).
// ---------------------------------------------------------------------------
__device__ __forceinline__ int detect_is64(const int* ei, int* s_flag) {
    if (threadIdx.x < 32) {
        const unsigned int* w = (const unsigned int*)ei;
        unsigned int v = w[2 * threadIdx.x + 1] | w[2 * (threadIdx.x + 32) + 1];
        int all0 = __all_sync(0xffffffffu, v == 0u);
        if (threadIdx.x == 0) *s_flag = all0;
    }
    __syncthreads();
    return *s_flag;
}

// Histogram + pack(dst, rank). 4 edges/thread for atomic MLP.
__global__ void hist_kernel(const int* __restrict__ ei, int E) {
    __shared__ int s_flag;
    bool is64 = detect_is64(ei, &s_flag);
    int base = (blockIdx.x * blockDim.x + threadIdx.x) * 4;
    if (base + 3 < E) {
        int d0, d1, d2, d3;
        if (is64) {
            const int2* p = (const int2*)(ei) + E + base;
            int2 a = p[0], b = p[1], c = p[2], d = p[3];
            d0 = a.x; d1 = b.x; d2 = c.x; d3 = d.x;
        } else {
            d0 = ei[E + base + 0]; d1 = ei[E + base + 1];
            d2 = ei[E + base + 2]; d3 = ei[E + base + 3];
        }
        unsigned int r0 = atomicAdd(&g_cnt[d0], 1);
        unsigned int r1 = atomicAdd(&g_cnt[d1], 1);
        unsigned int r2 = atomicAdd(&g_cnt[d2], 1);
        unsigned int r3 = atomicAdd(&g_cnt[d3], 1);
        g_pack[base + 0] = (unsigned int)d0 | (r0 << 16);
        g_pack[base + 1] = (unsigned int)d1 | (r1 << 16);
        g_pack[base + 2] = (unsigned int)d2 | (r2 << 16);
        g_pack[base + 3] = (unsigned int)d3 | (r3 << 16);
    } else {
        for (int j = 0; j < 4; j++) {
            int e = base + j;
            if (e < E) {
                int d = is64 ? ei[2 * E + 2 * e] : ei[E + e];
                unsigned int r = atomicAdd(&g_cnt[d], 1);
                g_pack[e] = (unsigned int)d | (r << 16);
            }
        }
    }
}

// ---------------------------------------------------------------------------
// Single-kernel exclusive scan (decoupled lookback, ticket-ordered).
// ---------------------------------------------------------------------------
__global__ void scan_kernel(int N) {
    __shared__ int s_bid;
    __shared__ int s_warp[8];
    __shared__ int s_exc;
    int t = threadIdx.x;
    if (t == 0) s_bid = atomicAdd(&g_ctl.ticket, 1);
    __syncthreads();
    int bid = s_bid;

    int base = bid * 1024 + t * 4;
    int v[4], tsum = 0;
#pragma unroll
    for (int j = 0; j < 4; j++) {
        int idx = base + j;
        v[j] = (idx < N) ? g_cnt[idx] : 0;
        tsum += v[j];
    }
    int lane = t & 31, w = t >> 5;
    int x = tsum;
#pragma unroll
    for (int o = 1; o < 32; o <<= 1) {
        int y = __shfl_up_sync(0xffffffffu, x, o);
        if (lane >= o) x += y;
    }
    if (lane == 31) s_warp[w] = x;
    __syncthreads();

    if (t == 0) {
        int total = 0;
#pragma unroll
        for (int i = 0; i < 8; i++) { int tmp = s_warp[i]; s_warp[i] = total; total += tmp; }
        int exc = 0;
        volatile int* state = g_ctl.state;
        if (bid == 0) {
            g_prefval[0] = total;
            __threadfence();
            state[0] = 2;
        } else {
            g_aggval[bid] = total;
            __threadfence();
            state[bid] = 1;
            int i = bid - 1;
            while (true) {
                int st;
                while ((st = state[i]) == 0) { }
                if (st == 2) { exc += g_prefval[i]; break; }
                exc += g_aggval[i];
                i--;
            }
            g_prefval[bid] = exc + total;
            __threadfence();
            state[bid] = 2;
        }
        s_exc = exc;
    }
    __syncthreads();

    int run = x - tsum + s_warp[w] + s_exc;
#pragma unroll
    for (int j = 0; j < 4; j++) {
        int idx = base + j;
        if (idx < N) {
            g_off[idx]  = run;
            g_dinv[idx] = rsqrtf((float)(v[j] + 1));   // +1 self loop
            run += v[j];
        }
    }
}

// Atomic-free CSR fill: pos = off[dst] + rank. Full-quad fast path.
__global__ void fill_kernel(const int* __restrict__ ei, int E) {
    __shared__ int s_flag;
    bool is64 = detect_is64(ei, &s_flag);
    int base = (blockIdx.x * blockDim.x + threadIdx.x) * 4;
    if (base + 3 < E) {
        int s0, s1, s2, s3;
        if (is64) {
            const int2* p = (const int2*)ei + base;
            int2 a = p[0], b = p[1], c = p[2], d = p[3];
            s0 = a.x; s1 = b.x; s2 = c.x; s3 = d.x;
        } else {
            s0 = ei[base + 0]; s1 = ei[base + 1];
            s2 = ei[base + 2]; s3 = ei[base + 3];
        }
        unsigned int p0 = g_pack[base + 0];
        unsigned int p1 = g_pack[base + 1];
        unsigned int p2 = g_pack[base + 2];
        unsigned int p3 = g_pack[base + 3];
        int o0 = g_off[p0 & 0xffffu];
        int o1 = g_off[p1 & 0xffffu];
        int o2 = g_off[p2 & 0xffffu];
        int o3 = g_off[p3 & 0xffffu];
        g_csr[o0 + (int)(p0 >> 16)] = s0;
        g_csr[o1 + (int)(p1 >> 16)] = s1;
        g_csr[o2 + (int)(p2 >> 16)] = s2;
        g_csr[o3 + (int)(p3 >> 16)] = s3;
    } else {
        for (int j = 0; j < 4; j++) {
            int e = base + j;
            if (e < E) {
                int s = is64 ? ei[2 * e] : ei[e];
                unsigned int p = g_pack[e];
                g_csr[g_off[p & 0xffffu] + (int)(p >> 16)] = s;
            }
        }
    }
}

// ---------------------------------------------------------------------------
// Gather: 8 threads/node, each owns 8 features = one uint4 of fp16 per edge.
// ---------------------------------------------------------------------------
__device__ __forceinline__ void acc8(float* a, uint4 r) {
    const unsigned int rr[4] = {r.x, r.y, r.z, r.w};
#pragma unroll
    for (int q = 0; q < 4; q++) {
        float2 f = __half22float2(*reinterpret_cast<const __half2*>(&rr[q]));
        a[2 * q]     += f.x;
        a[2 * q + 1] += f.y;
    }
}

__device__ __forceinline__ void gather_node(float* a, int gn, int lane) {
    const uint4* gh = (const uint4*)g_h;   // 8 uint4 per node row
#pragma unroll
    for (int j = 0; j < 8; j++) a[j] = 0.f;
    acc8(a, __ldg(gh + (size_t)gn * 8 + lane));   // self message
    int e = g_off[gn];
    int end = e + g_cnt[gn];
    for (; e + 4 <= end; e += 4) {
        int s0 = __ldg(&g_csr[e]);
        int s1 = __ldg(&g_csr[e + 1]);
        int s2 = __ldg(&g_csr[e + 2]);
        int s3 = __ldg(&g_csr[e + 3]);
        uint4 r0 = __ldg(gh + (size_t)s0 * 8 + lane);
        uint4 r1 = __ldg(gh + (size_t)s1 * 8 + lane);
        uint4 r2 = __ldg(gh + (size_t)s2 * 8 + lane);
        uint4 r3 = __ldg(gh + (size_t)s3 * 8 + lane);
        acc8(a, r0);
        acc8(a, r1);
        acc8(a, r2);
        acc8(a, r3);
    }
    for (; e < end; e++) {
        int s = __ldg(&g_csr[e]);
        acc8(a, __ldg(gh + (size_t)s * 8 + lane));
    }
}

// Aggregate: raw fp16 sums to g_a (epilogue applied by the next GEMM loader).
__global__ __launch_bounds__(256) void agg_kernel(int N) {
    int idx = blockIdx.x * blockDim.x + threadIdx.x;
    int node = idx >> 3, lane = idx & 7;
    if (node >= N) return;
    float a[8];
    gather_node(a, node, lane);
    unsigned int wbuf[4];
#pragma unroll
    for (int q = 0; q < 4; q++) {
        __half2 h = __floats2half2_rn(a[2 * q], a[2 * q + 1]);
        wbuf[q] = *reinterpret_cast<unsigned int*>(&h);
    }
    *(uint4*)(g_a + (size_t)node * H + lane * 8) =
        make_uint4(wbuf[0], wbuf[1], wbuf[2], wbuf[3]);
}

// Final aggregate fused with mean pooling column sums.
__global__ __launch_bounds__(256) void aggfinal_kernel(int N) {
    __shared__ float s_col[H];
    if (threadIdx.x < H) s_col[threadIdx.x] = 0.f;
    __syncthreads();

    int idx = blockIdx.x * blockDim.x + threadIdx.x;
    int node = idx >> 3, lane = idx & 7;
    if (node < N) {
        float a[8];
        gather_node(a, node, lane);
        float di = g_dinv[node];
#pragma unroll
        for (int j = 0; j < 8; j++)
            atomicAdd(&s_col[lane * 8 + j], a[j] * di);
    }
    __syncthreads();
    if (threadIdx.x < H) atomicAdd(&g_ctl.colsum[threadIdx.x], s_col[threadIdx.x]);
}

// ---------------------------------------------------------------------------
// Layer 1 GEMM: x[N,10] @ W1[10,64], scale by dinv, write fp16 messages.
// (K=10 too small for tensor cores; FFMA path is ~4us.)
// ---------------------------------------------------------------------------
__global__ __launch_bounds__(256) void gemm1_kernel(const float* __restrict__ X,
                                                    const float* __restrict__ W,
                                                    int N) {
    __shared__ float xs[64][12];
    __shared__ float ws[10][64];
    int node0 = blockIdx.x * 64;
    int t = threadIdx.x;

    for (int i = t; i < 640; i += 256) ws[i >> 6][i & 63] = W[i];
    for (int i = t; i < 640; i += 256) {
        int n = i / 10, k = i - n * 10;
        int gn = node0 + n;
        xs[n][k] = (gn < N) ? X[gn * 10 + k] : 0.f;
    }
    __syncthreads();

    int tx = t & 15, ty = t >> 4;
    float acc[4][4];
#pragma unroll
    for (int i = 0; i < 4; i++)
#pragma unroll
        for (int j = 0; j < 4; j++) acc[i][j] = 0.f;

#pragma unroll
    for (int k = 0; k < 10; k++) {
        float4 wv = *(const float4*)&ws[k][tx * 4];
#pragma unroll
        for (int i = 0; i < 4; i++) {
            float xa = xs[ty * 4 + i][k];
            acc[i][0] = fmaf(xa, wv.x, acc[i][0]);
            acc[i][1] = fmaf(xa, wv.y, acc[i][1]);
            acc[i][2] = fmaf(xa, wv.z, acc[i][2]);
            acc[i][3] = fmaf(xa, wv.w, acc[i][3]);
        }
    }

#pragma unroll
    for (int i = 0; i < 4; i++) {
        int gn = node0 + ty * 4 + i;
        if (gn < N) {
            float di = g_dinv[gn];
            __half2* hp = (__half2*)(g_h + (size_t)gn * H + tx * 4);
            hp[0] = __floats2half2_rn(acc[i][0] * di, acc[i][1] * di);
            hp[1] = __floats2half2_rn(acc[i][2] * di, acc[i][3] * di);
        }
    }
}

// ---------------------------------------------------------------------------
// Layers 2/3 GEMM on TENSOR CORES with SPLIT-W for precision:
//   W = W_hi + W_lo (both fp16);  X@W = X@W_hi + X@W_lo  (fp32 accumulate).
// W quantization error drops from ~2^-11 (systematic, fails) to ~2^-22.
// Input  = relu(g_a * dinv + bias_prev) in fp16 (random rounding, cancels).
// Output = (X@W) * dinv, written as fp16 messages to g_h.
// 64x64x64 per block, 8 warps, 2 output tiles (16x16) per warp, 8 MMAs each.
// ---------------------------------------------------------------------------
__global__ __launch_bounds__(256) void gemm2w_kernel(const float* __restrict__ W,
                                                     const float* __restrict__ bias_prev,
                                                     int N) {
    __shared__ __align__(16) __half xs[64][72];
    __shared__ __align__(16) __half whi[64][72];
    __shared__ __align__(16) __half wlo[64][72];
    __shared__ float os[64][68];
    __shared__ float bsh[64];

    int node0 = blockIdx.x * 64;
    int t = threadIdx.x;

    if (t < 64) bsh[t] = bias_prev[t];
    for (int i = t; i < 4096; i += 256) {
        float w = W[i];
        __half hi = __float2half(w);
        whi[i >> 6][i & 63] = hi;
        wlo[i >> 6][i & 63] = __float2half(w - __half2float(hi));
    }
    __syncthreads();   // bsh ready before epilogue loads use it

    // Load + epilogue: 512 chunks of 8 fp16 (2 per thread)
    for (int i = t; i < 512; i += 256) {
        int n = i >> 3, c = i & 7;
        int gn = node0 + n;
        if (gn < N) {
            uint4 r = __ldg((const uint4*)(g_a + (size_t)gn * H + c * 8));
            float di = g_dinv[gn];
            const unsigned int rr[4] = {r.x, r.y, r.z, r.w};
#pragma unroll
            for (int q = 0; q < 4; q++) {
                float2 f = __half22float2(*reinterpret_cast<const __half2*>(&rr[q]));
                xs[n][c * 8 + 2 * q] =
                    __float2half(fmaxf(fmaf(f.x, di, bsh[c * 8 + 2 * q]), 0.f));
                xs[n][c * 8 + 2 * q + 1] =
                    __float2half(fmaxf(fmaf(f.y, di, bsh[c * 8 + 2 * q + 1]), 0.f));
            }
        } else {
#pragma unroll
            for (int q = 0; q < 8; q++) xs[n][c * 8 + q] = __half(0.f);
        }
    }
    __syncthreads();

    // MMA: 16 tiles of 16x16; warp w handles tiles w and w+8.
    int wid = t >> 5;
#pragma unroll
    for (int rep = 0; rep < 2; rep++) {
        int tile = wid + rep * 8;
        int mi = tile >> 2, ni = tile & 3;
        wmma::fragment<wmma::accumulator, 16, 16, 16, float> c;
        wmma::fill_fragment(c, 0.f);
#pragma unroll
        for (int k0 = 0; k0 < 4; k0++) {
            wmma::fragment<wmma::matrix_a, 16, 16, 16, __half, wmma::row_major> a;
            wmma::fragment<wmma::matrix_b, 16, 16, 16, __half, wmma::row_major> bh;
            wmma::fragment<wmma::matrix_b, 16, 16, 16, __half, wmma::row_major> bl;
            wmma::load_matrix_sync(a, &xs[mi * 16][k0 * 16], 72);
            wmma::load_matrix_sync(bh, &whi[k0 * 16][ni * 16], 72);
            wmma::load_matrix_sync(bl, &wlo[k0 * 16][ni * 16], 72);
            wmma::mma_sync(c, a, bh, c);
            wmma::mma_sync(c, a, bl, c);
        }
        wmma::store_matrix_sync(&os[mi * 16][ni * 16], c, 68, wmma::mem_row_major);
    }
    __syncthreads();

    // Epilogue: scale by dinv, convert fp16, write messages.
    for (int i = t; i < 512; i += 256) {
        int n = i >> 3, c = i & 7;
        int gn = node0 + n;
        if (gn < N) {
            float di = g_dinv[gn];
            unsigned int wbuf[4];
#pragma unroll
            for (int q = 0; q < 4; q++) {
                __half2 h = __floats2half2_rn(os[n][c * 8 + 2 * q] * di,
                                              os[n][c * 8 + 2 * q + 1] * di);
                wbuf[q] = *reinterpret_cast<unsigned int*>(&h);
            }
            *(uint4*)(g_h + (size_t)gn * H + c * 8) =
                make_uint4(wbuf[0], wbuf[1], wbuf[2], wbuf[3]);
        }
    }
}

// out = (colsum/N + b3) . fcW + fcb
__global__ void final_kernel(const float* __restrict__ b3,
                             const float* __restrict__ fcW,
                             const float* __restrict__ fcb,
                             float* __restrict__ out, int N) {
    int f = threadIdx.x;  // 64 threads
    float v = (g_ctl.colsum[f] / (float)N + b3[f]) * fcW[f];
#pragma unroll
    for (int o = 16; o > 0; o >>= 1) v += __shfl_down_sync(0xffffffffu, v, o);
    __shared__ float p[2];
    if ((f & 31) == 0) p[f >> 5] = v;
    __syncthreads();
    if (f == 0) out[0] = p[0] + p[1] + fcb[0];
}

extern "C" void kernel_launch(void* const* d_in, const int* in_sizes, int n_in,
                              void* d_out, int out_size) {
    const float* x   = (const float*)d_in[0];
    const void*  ei  = d_in[1];
    const float* W1  = (const float*)d_in[2];
    const float* b1  = (const float*)d_in[3];
    const float* W2  = (const float*)d_in[4];
    const float* b2  = (const float*)d_in[5];
    const float* W3  = (const float*)d_in[6];
    const float* b3  = (const float*)d_in[7];
    const float* fcW = (const float*)d_in[8];
    const float* fcb = (const float*)d_in[9];
    float* out = (float*)d_out;

    int FIN1 = in_sizes[2] / H;      // 10
    int N = in_sizes[0] / FIN1;      // 50000
    int E = in_sizes[1] / 2;         // 800000

    int SB = (N + 1023) / 1024;              // scan blocks (<=64)
    int eblocks = (E + 1023) / 1024;         // 4 edges/thread
    int gblocks = (N + 63) / 64;
    int ablocks = (N * 8 + 255) / 256;

    // Zero counters + control block via memset nodes (capturable, no alloc).
    void* cnt_ptr = nullptr;
    void* ctl_ptr = nullptr;
    cudaGetSymbolAddress(&cnt_ptr, g_cnt);
    cudaGetSymbolAddress(&ctl_ptr, g_ctl);
    cudaMemsetAsync(cnt_ptr, 0, (size_t)N * sizeof(int));
    cudaMemsetAsync(ctl_ptr, 0, sizeof(Ctl));

    hist_kernel<<<eblocks, 256>>>((const int*)ei, E);
    scan_kernel<<<SB, 256>>>(N);
    fill_kernel<<<eblocks, 256>>>((const int*)ei, E);

    gemm1_kernel<<<gblocks, 256>>>(x, W1, N);      // -> g_h
    agg_kernel<<<ablocks, 256>>>(N);               // g_h -> g_a
    gemm2w_kernel<<<gblocks, 256>>>(W2, b1, N);    // g_a -> g_h (split-W TC)
    agg_kernel<<<ablocks, 256>>>(N);               // g_h -> g_a
    gemm2w_kernel<<<gblocks, 256>>>(W3, b2, N);    // g_a -> g_h (split-W TC)
    aggfinal_kernel<<<ablocks, 256>>>(N);          // g_h -> colsum
    final_kernel<<<1, 64>>>(b3, fcW, fcb, out, N);
}